// round 6
// baseline (speedup 1.0000x reference)
#include <cuda_runtime.h>

#define R 2048
#define T 4096
#define NBLK 128
#define NTHREADS 256

// Scratch (static __device__ arrays — no allocation anywhere)
__device__ float g_B[(size_t)T * R];   // 32 MB: precomputed input+feedback bias
__device__ float g_X[(size_t)T * R];   // 32 MB: reservoir states (row 0 = zeros)
__device__ int   g_flag[NBLK];         // per-producer progress flags (monotone)

__device__ __forceinline__ int ld_acq(const int* p) {
    int v;
    asm volatile("ld.global.acquire.gpu.b32 %0, [%1];" : "=r"(v) : "l"(p) : "memory");
    return v;
}

__device__ __forceinline__ void st_rel(int* p, int v) {
    asm volatile("st.release.gpu.global.b32 [%0], %1;" :: "l"(p), "r"(v) : "memory");
}

// packed dual-FMA: acc = a*b + acc on (f32,f32) pairs held in u64
__device__ __forceinline__ void fma2(unsigned long long& acc,
                                     unsigned long long a,
                                     unsigned long long b) {
    asm volatile("fma.rn.f32x2 %0, %1, %2, %0;" : "+l"(acc) : "l"(a), "l"(b));
}

__device__ __forceinline__ unsigned long long addx2(unsigned long long a,
                                                    unsigned long long b) {
    unsigned long long d;
    asm volatile("add.rn.f32x2 %0, %1, %2;" : "=l"(d) : "l"(a), "l"(b));
    return d;
}

__device__ __forceinline__ float lo_f(unsigned long long v) {
    return __uint_as_float((unsigned)(v & 0xffffffffull));
}
__device__ __forceinline__ float hi_f(unsigned long long v) {
    return __uint_as_float((unsigned)(v >> 32));
}

__device__ __forceinline__ unsigned long long pack2(float a, float b) {
    unsigned long long d;
    asm("mov.b64 %0, {%1, %2};" : "=l"(d) : "f"(a), "f"(b));
    return d;
}

// fast tanh: 1 - 2/(e^{2x}+1); correct +-1 limits, rel err ~1e-6
__device__ __forceinline__ float fast_tanh(float x) {
    float e = __expf(2.0f * x);
    return 1.0f - __fdividef(2.0f, e + 1.0f);
}

// ---------------------------------------------------------------------------
// Kernel 0: reset flags + zero state row 0 (runs every launch: graph-safe)
// ---------------------------------------------------------------------------
__global__ void init_kernel() {
    int tid = blockIdx.x * blockDim.x + threadIdx.x;
    int stride = gridDim.x * blockDim.x;
    for (int b = tid; b < NBLK; b += stride) g_flag[b] = 0;
    for (int i = tid; i < R; i += stride) g_X[i] = 0.0f;
}

// ---------------------------------------------------------------------------
// Kernel 1: B[n][i] = w_in[i,:]@inputs[n] + w_feedb[i,:]@outputs[n-1], n>=1
// ---------------------------------------------------------------------------
__global__ void precomp_kernel(const float* __restrict__ inputs,
                               const float* __restrict__ outputs,
                               const float* __restrict__ w_in,
                               const float* __restrict__ w_feedb) {
    const int i = blockIdx.x * 256 + threadIdx.x;  // 0..2047 (grid.x = 8)
    float wi[8], wf[4];
#pragma unroll
    for (int k = 0; k < 8; k++) wi[k] = w_in[i * 8 + k];
#pragma unroll
    for (int k = 0; k < 4; k++) wf[k] = w_feedb[i * 4 + k];
    int n0 = blockIdx.y * 128;          // grid.y = 32
    int n1 = n0 + 128;
    if (n0 == 0) n0 = 1;
    for (int n = n0; n < n1; n++) {
        float s = 0.0f;
#pragma unroll
        for (int k = 0; k < 8; k++) s = fmaf(wi[k], inputs[n * 8 + k], s);
#pragma unroll
        for (int k = 0; k < 4; k++) s = fmaf(wf[k], outputs[(n - 1) * 4 + k], s);
        g_B[(size_t)n * R + i] = s;
    }
}

// ---------------------------------------------------------------------------
// Kernel 2: persistent recurrence. 128 blocks x 256 threads.
// Block b owns rows [16b, 16b+16).
// Warp (g = warp>>1, c = warp&1): 4 rows x 1024-float x-chunk.
// Sync: per-producer release flags. Each warp acquire-polls ONLY the 64
// flags covering its chunk (2 loads/lane), then loads x and computes.
// Cross-warp combine via parity-double-buffered SMEM; warp 0 finalizes
// (tanh + 16 STG.32 + __syncwarp + st.release flag[blk]).
// ---------------------------------------------------------------------------
__global__ __launch_bounds__(NTHREADS, 1)
void recur_kernel(const float* __restrict__ w, const float* __restrict__ noise) {
    const int tid  = threadIdx.x;
    const int warp = tid >> 5;
    const int lane = tid & 31;
    const int g    = warp >> 1;      // row-group 0..3
    const int c    = warp & 1;       // x-chunk 0..1
    const int base = blockIdx.x * 16;
    const int R0   = base + g * 4;   // first of this warp's 4 rows

    // W registers: 4 rows x 8 slots (each slot = 4 floats = ulonglong2)
    ulonglong2 Wr[4][8];
#pragma unroll
    for (int r = 0; r < 4; ++r) {
        const ulonglong2* wp =
            reinterpret_cast<const ulonglong2*>(w + (size_t)(R0 + r) * R);
#pragma unroll
        for (int j = 0; j < 8; ++j)
            Wr[r][j] = wp[256 * c + lane + 32 * j];
    }

    // flags this warp must see before reading its chunk
    const int* fp = &g_flag[64 * c + lane];

    __shared__ float4 sm_part[2][2][4];  // [step parity][chunk][row-group]

    for (int n = 1; n < T; ++n) {
        // Prefetch bias + noise for the finalizer lanes (independent of x)
        float bnv = 0.f, nzv = 0.f;
        if (warp == 0 && lane < 16) {
            bnv = g_B[(size_t)n * R + base + lane];
            nzv = noise[(size_t)n * R + base + lane];
        }

        // Wait until all 64 producers of this chunk have published step n-1.
        const int nm1 = n - 1;
        for (;;) {
            int f0 = ld_acq(fp);
            int f1 = ld_acq(fp + 32);
            if (__all_sync(0xffffffffu, (f0 >= nm1) & (f1 >= nm1))) break;
        }

        const ulonglong2* x2 =
            reinterpret_cast<const ulonglong2*>(g_X + (size_t)(n - 1) * R)
            + 256 * c + lane;

        unsigned long long acc[4][2];
#pragma unroll
        for (int r = 0; r < 4; ++r) { acc[r][0] = 0ull; acc[r][1] = 0ull; }
#pragma unroll
        for (int j = 0; j < 8; ++j) {
            ulonglong2 xv = x2[32 * j];
#pragma unroll
            for (int r = 0; r < 4; ++r) {
                fma2(acc[r][0], Wr[r][j].x, xv.x);
                fma2(acc[r][1], Wr[r][j].y, xv.y);
            }
        }

        // per-row lane-local sum, packed as (row0,row1) and (row2,row3)
        float s[4];
#pragma unroll
        for (int r = 0; r < 4; ++r) {
            unsigned long long t = addx2(acc[r][0], acc[r][1]);
            s[r] = lo_f(t) + hi_f(t);
        }
        unsigned long long p01 = pack2(s[0], s[1]);
        unsigned long long p23 = pack2(s[2], s[3]);
#pragma unroll
        for (int off = 16; off > 0; off >>= 1) {
            p01 = addx2(p01, __shfl_xor_sync(0xffffffffu, p01, off));
            p23 = addx2(p23, __shfl_xor_sync(0xffffffffu, p23, off));
        }
        const int par = n & 1;
        if (lane == 0)
            sm_part[par][c][g] =
                make_float4(lo_f(p01), hi_f(p01), lo_f(p23), hi_f(p23));
        __syncthreads();

        // Warp 0 finalizes all 16 rows, then releases this block's flag.
        if (warp == 0) {
            if (lane < 16) {
                const float* f0 = reinterpret_cast<const float*>(&sm_part[par][0][0]);
                const float* f1 = reinterpret_cast<const float*>(&sm_part[par][1][0]);
                float v = fast_tanh(f0[lane] + f1[lane] + bnv) + nzv;
                g_X[(size_t)n * R + base + lane] = v;
            }
            __syncwarp();
            if (lane == 0)
                st_rel(&g_flag[blockIdx.x], n);  // stores ordered via syncwarp
        }
    }
}

// ---------------------------------------------------------------------------
// Kernel 3: readout. out[n] = lin_w[:, :R]@x_n + lin_w[:, R:]@u_n + lin_b
// One block per n, 256 threads.
// ---------------------------------------------------------------------------
__global__ void readout_kernel(const float* __restrict__ inputs,
                               const float* __restrict__ lin_w,
                               const float* __restrict__ lin_b,
                               float* __restrict__ out) {
    const int n   = blockIdx.x;
    const int tid = threadIdx.x;
    if (n == 0) {
        if (tid < 4) out[tid] = lin_b[tid];
        return;
    }
    const int FAN = R + 8;  // 2056
    float acc0 = 0.f, acc1 = 0.f, acc2 = 0.f, acc3 = 0.f;
    const float* xr = g_X + (size_t)n * R;
    for (int i = tid; i < R; i += 256) {
        float xv = xr[i];
        acc0 = fmaf(lin_w[0 * FAN + i], xv, acc0);
        acc1 = fmaf(lin_w[1 * FAN + i], xv, acc1);
        acc2 = fmaf(lin_w[2 * FAN + i], xv, acc2);
        acc3 = fmaf(lin_w[3 * FAN + i], xv, acc3);
    }
#pragma unroll
    for (int off = 16; off > 0; off >>= 1) {
        acc0 += __shfl_xor_sync(0xffffffffu, acc0, off);
        acc1 += __shfl_xor_sync(0xffffffffu, acc1, off);
        acc2 += __shfl_xor_sync(0xffffffffu, acc2, off);
        acc3 += __shfl_xor_sync(0xffffffffu, acc3, off);
    }
    __shared__ float red[8][4];
    int warp = tid >> 5, lane = tid & 31;
    if (lane == 0) {
        red[warp][0] = acc0; red[warp][1] = acc1;
        red[warp][2] = acc2; red[warp][3] = acc3;
    }
    __syncthreads();
    if (tid < 4) {
        float s = 0.f;
#pragma unroll
        for (int wp = 0; wp < 8; wp++) s += red[wp][tid];
        float inp = 0.f;
#pragma unroll
        for (int k = 0; k < 8; k++)
            inp = fmaf(lin_w[tid * FAN + R + k], inputs[n * 8 + k], inp);
        out[n * 4 + tid] = s + inp + lin_b[tid];
    }
}

// ---------------------------------------------------------------------------
// Launch: init -> precompute B -> persistent recurrence -> readout
// ---------------------------------------------------------------------------
extern "C" void kernel_launch(void* const* d_in, const int* in_sizes, int n_in,
                              void* d_out, int out_size) {
    const float* inputs  = (const float*)d_in[0];
    const float* outputs = (const float*)d_in[1];
    const float* w       = (const float*)d_in[2];
    const float* w_in    = (const float*)d_in[3];
    const float* w_feedb = (const float*)d_in[4];
    const float* lin_w   = (const float*)d_in[5];
    const float* lin_b   = (const float*)d_in[6];
    const float* noise   = (const float*)d_in[7];
    float* out = (float*)d_out;

    init_kernel<<<8, 256>>>();
    precomp_kernel<<<dim3(8, 32), 256>>>(inputs, outputs, w_in, w_feedb);
    recur_kernel<<<NBLK, NTHREADS>>>(w, noise);
    readout_kernel<<<T, 256>>>(inputs, lin_w, lin_b, out);
}

// round 7
// speedup vs baseline: 3.3845x; 3.3845x over previous
#include <cuda_runtime.h>

#define R 2048
#define T 4096
#define NBLK 128
#define NTHREADS 256

// Scratch (static __device__ arrays — no allocation anywhere)
__device__ float g_B[(size_t)T * R];    // 32 MB: precomputed input+feedback bias
__device__ float g_X[(size_t)T * R];    // 32 MB: reservoir states (row 0 = zeros)
__device__ int   g_cnt[T][256];         // per-step counter tree: slot j at [n][j*32]
                                        // (8 counters/step, 128B apart; target 32)

__device__ __forceinline__ int ld_acq(const int* p) {
    int v;
    asm volatile("ld.global.acquire.gpu.b32 %0, [%1];" : "=r"(v) : "l"(p) : "memory");
    return v;
}

__device__ __forceinline__ void red_release_add(int* p, int v) {
    asm volatile("red.release.gpu.global.add.u32 [%0], %1;" :: "l"(p), "r"(v) : "memory");
}

// packed dual-FMA: acc = a*b + acc on (f32,f32) pairs held in u64
__device__ __forceinline__ void fma2(unsigned long long& acc,
                                     unsigned long long a,
                                     unsigned long long b) {
    asm volatile("fma.rn.f32x2 %0, %1, %2, %0;" : "+l"(acc) : "l"(a), "l"(b));
}

__device__ __forceinline__ unsigned long long addx2(unsigned long long a,
                                                    unsigned long long b) {
    unsigned long long d;
    asm volatile("add.rn.f32x2 %0, %1, %2;" : "=l"(d) : "l"(a), "l"(b));
    return d;
}

__device__ __forceinline__ float lo_f(unsigned long long v) {
    return __uint_as_float((unsigned)(v & 0xffffffffull));
}
__device__ __forceinline__ float hi_f(unsigned long long v) {
    return __uint_as_float((unsigned)(v >> 32));
}

__device__ __forceinline__ unsigned long long pack2(float a, float b) {
    unsigned long long d;
    asm("mov.b64 %0, {%1, %2};" : "=l"(d) : "f"(a), "f"(b));
    return d;
}

// fast tanh: 1 - 2/(e^{2x}+1); correct +-1 limits, rel err ~1e-6
__device__ __forceinline__ float fast_tanh(float x) {
    float e = __expf(2.0f * x);
    return 1.0f - __fdividef(2.0f, e + 1.0f);
}

// ---------------------------------------------------------------------------
// Kernel 0: zero counters (step 0 slots pre-armed to 32), zero g_X row 0.
// Runs every launch: graph-safe, deterministic.
// ---------------------------------------------------------------------------
__global__ void init_kernel() {
    int tid = blockIdx.x * blockDim.x + threadIdx.x;
    int stride = gridDim.x * blockDim.x;
    int* cnt = &g_cnt[0][0];
    const int total = T * 256;
    for (int i = tid; i < total; i += stride) {
        int v = 0;
        if (i < 256 && (i & 31) == 0) v = 32;   // g_cnt[0][j*32] = 32, j<8
        cnt[i] = v;
    }
    for (int i = tid; i < R; i += stride) g_X[i] = 0.0f;
}

// ---------------------------------------------------------------------------
// Kernel 1: B[n][i] = w_in[i,:]@inputs[n] + w_feedb[i,:]@outputs[n-1], n>=1
// ---------------------------------------------------------------------------
__global__ void precomp_kernel(const float* __restrict__ inputs,
                               const float* __restrict__ outputs,
                               const float* __restrict__ w_in,
                               const float* __restrict__ w_feedb) {
    const int i = blockIdx.x * 256 + threadIdx.x;  // 0..2047 (grid.x = 8)
    float wi[8], wf[4];
#pragma unroll
    for (int k = 0; k < 8; k++) wi[k] = w_in[i * 8 + k];
#pragma unroll
    for (int k = 0; k < 4; k++) wf[k] = w_feedb[i * 4 + k];
    int n0 = blockIdx.y * 128;          // grid.y = 32
    int n1 = n0 + 128;
    if (n0 == 0) n0 = 1;
    for (int n = n0; n < n1; n++) {
        float s = 0.0f;
#pragma unroll
        for (int k = 0; k < 8; k++) s = fmaf(wi[k], inputs[n * 8 + k], s);
#pragma unroll
        for (int k = 0; k < 4; k++) s = fmaf(wf[k], outputs[(n - 1) * 4 + k], s);
        g_B[(size_t)n * R + i] = s;
    }
}

// ---------------------------------------------------------------------------
// Kernel 2: persistent recurrence. 128 blocks x 256 threads.
// Block b owns rows [16b, 16b+16).
// Warp (g = warp>>2 in {0,1}, c = warp&3 in {0..3}): 8 rows x 512-float chunk.
// x duplication per SM: 2x (16 KB/step through L1tex).
// Sync: ONE spinner warp per block (warp 0, lanes 0-7 poll the 8 per-step
// counters); producers release via warps 0 and 1 (8 rows each) into
// g_cnt[n][(blk>>4)*32] -> per-counter target 32.
// ---------------------------------------------------------------------------
__global__ __launch_bounds__(NTHREADS, 1)
void recur_kernel(const float* __restrict__ w, const float* __restrict__ noise) {
    const int tid  = threadIdx.x;
    const int warp = tid >> 5;
    const int lane = tid & 31;
    const int g    = warp >> 2;      // row-group 0..1 (8 rows)
    const int c    = warp & 3;       // x-chunk 0..3 (512 floats)
    const int base = blockIdx.x * 16;
    const int R0   = base + g * 8;   // first of this warp's 8 rows
    const int jrel = (blockIdx.x >> 4) * 32;   // this block's counter slot

    // W registers: 8 rows x 4 slots (each slot = 4 floats = ulonglong2)
    ulonglong2 Wr[8][4];
#pragma unroll
    for (int r = 0; r < 8; ++r) {
        const ulonglong2* wp =
            reinterpret_cast<const ulonglong2*>(w + (size_t)(R0 + r) * R);
#pragma unroll
        for (int j = 0; j < 4; ++j)
            Wr[r][j] = wp[128 * c + lane + 32 * j];
    }

    __shared__ float4 sm_part[2][4][2][2];  // [parity][chunk][group][half]

    for (int n = 1; n < T; ++n) {
        const int par = n & 1;

        // Prefetch bias + noise for the finalizer lanes (independent of x)
        float bnv = 0.f, nzv = 0.f;
        if (warp < 2 && lane < 8) {
            const int row = base + 8 * warp + lane;
            bnv = g_B[(size_t)n * R + row];
            nzv = noise[(size_t)n * R + row];
        }

        // Single spinner warp: lanes 0-7 poll the 8 counters of step n-1.
        if (warp == 0 && lane < 8) {
            const int* fp = &g_cnt[n - 1][lane * 32];
            for (;;) {
                int v = ld_acq(fp);
                if (__all_sync(0x000000ffu, v >= 32)) break;
            }
        }
        __syncthreads();

        // Load own x-chunk (512 floats -> 4 LDG.128/lane) and accumulate.
        const ulonglong2* x2 =
            reinterpret_cast<const ulonglong2*>(g_X + (size_t)(n - 1) * R)
            + 128 * c + lane;

        unsigned long long acc[8];
#pragma unroll
        for (int r = 0; r < 8; ++r) acc[r] = 0ull;
#pragma unroll
        for (int j = 0; j < 4; ++j) {
            ulonglong2 xv = x2[32 * j];
#pragma unroll
            for (int r = 0; r < 8; ++r) {
                fma2(acc[r], Wr[r][j].x, xv.x);
                fma2(acc[r], Wr[r][j].y, xv.y);
            }
        }

        // lane-local row sums, packed in pairs -> 4 u64 butterfly values
        float s[8];
#pragma unroll
        for (int r = 0; r < 8; ++r) s[r] = lo_f(acc[r]) + hi_f(acc[r]);
        unsigned long long p0 = pack2(s[0], s[1]);
        unsigned long long p1 = pack2(s[2], s[3]);
        unsigned long long p2 = pack2(s[4], s[5]);
        unsigned long long p3 = pack2(s[6], s[7]);
#pragma unroll
        for (int off = 16; off > 0; off >>= 1) {
            p0 = addx2(p0, __shfl_xor_sync(0xffffffffu, p0, off));
            p1 = addx2(p1, __shfl_xor_sync(0xffffffffu, p1, off));
            p2 = addx2(p2, __shfl_xor_sync(0xffffffffu, p2, off));
            p3 = addx2(p3, __shfl_xor_sync(0xffffffffu, p3, off));
        }
        if (lane == 0) {
            sm_part[par][c][g][0] =
                make_float4(lo_f(p0), hi_f(p0), lo_f(p1), hi_f(p1));
            sm_part[par][c][g][1] =
                make_float4(lo_f(p2), hi_f(p2), lo_f(p3), hi_f(p3));
        }
        __syncthreads();

        // Warps 0 and 1 finalize 8 rows each, then each releases +1.
        if (warp < 2) {
            if (lane < 8) {
                const float* q0 = reinterpret_cast<const float*>(&sm_part[par][0][warp][0]);
                const float* q1 = reinterpret_cast<const float*>(&sm_part[par][1][warp][0]);
                const float* q2 = reinterpret_cast<const float*>(&sm_part[par][2][warp][0]);
                const float* q3 = reinterpret_cast<const float*>(&sm_part[par][3][warp][0]);
                float v = fast_tanh(q0[lane] + q1[lane] + q2[lane] + q3[lane] + bnv) + nzv;
                g_X[(size_t)n * R + base + 8 * warp + lane] = v;
            }
            __syncwarp();
            if (lane == 0)
                red_release_add(&g_cnt[n][jrel], 1);  // stores ordered via syncwarp
        }
    }
}

// ---------------------------------------------------------------------------
// Kernel 3: readout. out[n] = lin_w[:, :R]@x_n + lin_w[:, R:]@u_n + lin_b
// One block per n, 256 threads.
// ---------------------------------------------------------------------------
__global__ void readout_kernel(const float* __restrict__ inputs,
                               const float* __restrict__ lin_w,
                               const float* __restrict__ lin_b,
                               float* __restrict__ out) {
    const int n   = blockIdx.x;
    const int tid = threadIdx.x;
    if (n == 0) {
        if (tid < 4) out[tid] = lin_b[tid];
        return;
    }
    const int FAN = R + 8;  // 2056
    float acc0 = 0.f, acc1 = 0.f, acc2 = 0.f, acc3 = 0.f;
    const float* xr = g_X + (size_t)n * R;
    for (int i = tid; i < R; i += 256) {
        float xv = xr[i];
        acc0 = fmaf(lin_w[0 * FAN + i], xv, acc0);
        acc1 = fmaf(lin_w[1 * FAN + i], xv, acc1);
        acc2 = fmaf(lin_w[2 * FAN + i], xv, acc2);
        acc3 = fmaf(lin_w[3 * FAN + i], xv, acc3);
    }
#pragma unroll
    for (int off = 16; off > 0; off >>= 1) {
        acc0 += __shfl_xor_sync(0xffffffffu, acc0, off);
        acc1 += __shfl_xor_sync(0xffffffffu, acc1, off);
        acc2 += __shfl_xor_sync(0xffffffffu, acc2, off);
        acc3 += __shfl_xor_sync(0xffffffffu, acc3, off);
    }
    __shared__ float red[8][4];
    int warp = tid >> 5, lane = tid & 31;
    if (lane == 0) {
        red[warp][0] = acc0; red[warp][1] = acc1;
        red[warp][2] = acc2; red[warp][3] = acc3;
    }
    __syncthreads();
    if (tid < 4) {
        float s = 0.f;
#pragma unroll
        for (int wp = 0; wp < 8; wp++) s += red[wp][tid];
        float inp = 0.f;
#pragma unroll
        for (int k = 0; k < 8; k++)
            inp = fmaf(lin_w[tid * FAN + R + k], inputs[n * 8 + k], inp);
        out[n * 4 + tid] = s + inp + lin_b[tid];
    }
}

// ---------------------------------------------------------------------------
// Launch: init -> precompute B -> persistent recurrence -> readout
// ---------------------------------------------------------------------------
extern "C" void kernel_launch(void* const* d_in, const int* in_sizes, int n_in,
                              void* d_out, int out_size) {
    const float* inputs  = (const float*)d_in[0];
    const float* outputs = (const float*)d_in[1];
    const float* w       = (const float*)d_in[2];
    const float* w_in    = (const float*)d_in[3];
    const float* w_feedb = (const float*)d_in[4];
    const float* lin_w   = (const float*)d_in[5];
    const float* lin_b   = (const float*)d_in[6];
    const float* noise   = (const float*)d_in[7];
    float* out = (float*)d_out;

    init_kernel<<<128, 256>>>();
    precomp_kernel<<<dim3(8, 32), 256>>>(inputs, outputs, w_in, w_feedb);
    recur_kernel<<<NBLK, NTHREADS>>>(w, noise);
    readout_kernel<<<T, 256>>>(inputs, lin_w, lin_b, out);
}

// round 8
// speedup vs baseline: 3.5626x; 1.0526x over previous
#include <cuda_runtime.h>

#define R 2048
#define T 4096
#define NBLK 128
#define NTHREADS 256

// Scratch (static __device__ arrays — no allocation anywhere)
__device__ float g_B[(size_t)T * R];   // 32 MB: precomputed input+feedback bias
__device__ float g_X[(size_t)T * R];   // 32 MB: reservoir states (row 0 = zeros)
__device__ int   g_done[T];            // per-step arrival counters

__device__ __forceinline__ int ld_acq(const int* p) {
    int v;
    asm volatile("ld.global.acquire.gpu.b32 %0, [%1];" : "=r"(v) : "l"(p) : "memory");
    return v;
}

__device__ __forceinline__ void red_release_add(int* p, int v) {
    asm volatile("red.release.gpu.global.add.u32 [%0], %1;" :: "l"(p), "r"(v) : "memory");
}

// packed dual-FMA: acc = a*b + acc on (f32,f32) pairs held in u64
__device__ __forceinline__ void fma2(unsigned long long& acc,
                                     unsigned long long a,
                                     unsigned long long b) {
    asm volatile("fma.rn.f32x2 %0, %1, %2, %0;" : "+l"(acc) : "l"(a), "l"(b));
}

__device__ __forceinline__ unsigned long long addx2(unsigned long long a,
                                                    unsigned long long b) {
    unsigned long long d;
    asm volatile("add.rn.f32x2 %0, %1, %2;" : "=l"(d) : "l"(a), "l"(b));
    return d;
}

__device__ __forceinline__ float lo_f(unsigned long long v) {
    return __uint_as_float((unsigned)(v & 0xffffffffull));
}
__device__ __forceinline__ float hi_f(unsigned long long v) {
    return __uint_as_float((unsigned)(v >> 32));
}

__device__ __forceinline__ unsigned long long pack2(float a, float b) {
    unsigned long long d;
    asm("mov.b64 %0, {%1, %2};" : "=l"(d) : "f"(a), "f"(b));
    return d;
}

// fast tanh: 1 - 2/(e^{2x}+1); correct +-1 limits, rel err ~1e-6
__device__ __forceinline__ float fast_tanh(float x) {
    float e = __expf(2.0f * x);
    return 1.0f - __fdividef(2.0f, e + 1.0f);
}

// ---------------------------------------------------------------------------
// Kernel 0: reset counters + zero state row 0 (runs every launch: graph-safe)
// ---------------------------------------------------------------------------
__global__ void init_kernel() {
    int tid = blockIdx.x * blockDim.x + threadIdx.x;
    int stride = gridDim.x * blockDim.x;
    for (int n = tid; n < T; n += stride) g_done[n] = (n == 0) ? NBLK : 0;
    for (int i = tid; i < R; i += stride) g_X[i] = 0.0f;
}

// ---------------------------------------------------------------------------
// Kernel 1: B[n][i] = w_in[i,:]@inputs[n] + w_feedb[i,:]@outputs[n-1], n>=1
// ---------------------------------------------------------------------------
__global__ void precomp_kernel(const float* __restrict__ inputs,
                               const float* __restrict__ outputs,
                               const float* __restrict__ w_in,
                               const float* __restrict__ w_feedb) {
    const int i = blockIdx.x * 256 + threadIdx.x;  // 0..2047 (grid.x = 8)
    float wi[8], wf[4];
#pragma unroll
    for (int k = 0; k < 8; k++) wi[k] = w_in[i * 8 + k];
#pragma unroll
    for (int k = 0; k < 4; k++) wf[k] = w_feedb[i * 4 + k];
    int n0 = blockIdx.y * 128;          // grid.y = 32
    int n1 = n0 + 128;
    if (n0 == 0) n0 = 1;
    for (int n = n0; n < n1; n++) {
        float s = 0.0f;
#pragma unroll
        for (int k = 0; k < 8; k++) s = fmaf(wi[k], inputs[n * 8 + k], s);
#pragma unroll
        for (int k = 0; k < 4; k++) s = fmaf(wf[k], outputs[(n - 1) * 4 + k], s);
        g_B[(size_t)n * R + i] = s;
    }
}

// ---------------------------------------------------------------------------
// Kernel 2: persistent recurrence. 128 blocks x 256 threads.
// Block b owns rows [16b, 16b+16).
// Warp (g = warp>>2 in {0,1}, c = warp&3 in {0..3}): 8 rows x 512-float chunk.
// Per-block x traffic halves vs half-chunk layout (each x word read twice,
// not four times). Sync protocol is EXACTLY R4's proven shape:
// tid 0 spins on ONE counter, __syncthreads broadcast, warp 0 finalizes all
// 16 rows, single red.release per block.
// ---------------------------------------------------------------------------
__global__ __launch_bounds__(NTHREADS, 1)
void recur_kernel(const float* __restrict__ w, const float* __restrict__ noise) {
    const int tid  = threadIdx.x;
    const int warp = tid >> 5;
    const int lane = tid & 31;
    const int g    = warp >> 2;      // row-group 0..1 (8 rows each)
    const int c    = warp & 3;       // x-chunk 0..3 (512 floats each)
    const int base = blockIdx.x * 16;
    const int R0   = base + g * 8;   // first of this warp's 8 rows

    // W registers: 8 rows x 4 slots (each slot = 4 floats = ulonglong2)
    ulonglong2 Wr[8][4];
#pragma unroll
    for (int r = 0; r < 8; ++r) {
        const ulonglong2* wp =
            reinterpret_cast<const ulonglong2*>(w + (size_t)(R0 + r) * R);
#pragma unroll
        for (int j = 0; j < 4; ++j)
            Wr[r][j] = wp[128 * c + lane + 32 * j];
    }

    __shared__ float sm_part[2][4][2][8];  // [parity][chunk][group][row-in-group]

    for (int n = 1; n < T; ++n) {
        const int par = n & 1;

        // Prefetch bias + noise for the finalizer lanes (independent of x)
        float bnv = 0.f, nzv = 0.f;
        if (warp == 0 && lane < 16) {
            bnv = g_B[(size_t)n * R + base + lane];
            nzv = noise[(size_t)n * R + base + lane];
        }

        // Single spinner per block; everyone else parks at the barrier.
        if (tid == 0) {
            const int* flag = &g_done[n - 1];
            while (ld_acq(flag) < NBLK) {}
        }
        __syncthreads();

        // Load own x-chunk (512 floats -> 4 LDG.128/lane) and accumulate.
        const ulonglong2* x2 =
            reinterpret_cast<const ulonglong2*>(g_X + (size_t)(n - 1) * R)
            + 128 * c + lane;

        unsigned long long acc[8];
#pragma unroll
        for (int r = 0; r < 8; ++r) acc[r] = 0ull;
#pragma unroll
        for (int j = 0; j < 4; ++j) {
            ulonglong2 xv = x2[32 * j];
#pragma unroll
            for (int r = 0; r < 8; ++r) {
                fma2(acc[r], Wr[r][j].x, xv.x);
                fma2(acc[r], Wr[r][j].y, xv.y);
            }
        }

        // lane-local row sums, packed in pairs -> 4 u64 butterfly values
        float s[8];
#pragma unroll
        for (int r = 0; r < 8; ++r) s[r] = lo_f(acc[r]) + hi_f(acc[r]);
        unsigned long long p0 = pack2(s[0], s[1]);
        unsigned long long p1 = pack2(s[2], s[3]);
        unsigned long long p2 = pack2(s[4], s[5]);
        unsigned long long p3 = pack2(s[6], s[7]);
#pragma unroll
        for (int off = 16; off > 0; off >>= 1) {
            p0 = addx2(p0, __shfl_xor_sync(0xffffffffu, p0, off));
            p1 = addx2(p1, __shfl_xor_sync(0xffffffffu, p1, off));
            p2 = addx2(p2, __shfl_xor_sync(0xffffffffu, p2, off));
            p3 = addx2(p3, __shfl_xor_sync(0xffffffffu, p3, off));
        }
        if (lane == 0) {
            float4* dst = reinterpret_cast<float4*>(&sm_part[par][c][g][0]);
            dst[0] = make_float4(lo_f(p0), hi_f(p0), lo_f(p1), hi_f(p1));
            dst[1] = make_float4(lo_f(p2), hi_f(p2), lo_f(p3), hi_f(p3));
        }
        __syncthreads();

        // Warp 0 finalizes all 16 rows: sum 4 chunks, tanh, store, publish.
        if (warp == 0) {
            if (lane < 16) {
                const int gg = lane >> 3, rr = lane & 7;
                float v = fast_tanh(sm_part[par][0][gg][rr] +
                                    sm_part[par][1][gg][rr] +
                                    sm_part[par][2][gg][rr] +
                                    sm_part[par][3][gg][rr] + bnv) + nzv;
                g_X[(size_t)n * R + base + lane] = v;
            }
            __syncwarp();
            if (lane == 0)
                red_release_add(&g_done[n], 1);  // stores ordered via syncwarp
        }
    }
}

// ---------------------------------------------------------------------------
// Kernel 3: readout. out[n] = lin_w[:, :R]@x_n + lin_w[:, R:]@u_n + lin_b
// One block per n, 256 threads.
// ---------------------------------------------------------------------------
__global__ void readout_kernel(const float* __restrict__ inputs,
                               const float* __restrict__ lin_w,
                               const float* __restrict__ lin_b,
                               float* __restrict__ out) {
    const int n   = blockIdx.x;
    const int tid = threadIdx.x;
    if (n == 0) {
        if (tid < 4) out[tid] = lin_b[tid];
        return;
    }
    const int FAN = R + 8;  // 2056
    float acc0 = 0.f, acc1 = 0.f, acc2 = 0.f, acc3 = 0.f;
    const float* xr = g_X + (size_t)n * R;
    for (int i = tid; i < R; i += 256) {
        float xv = xr[i];
        acc0 = fmaf(lin_w[0 * FAN + i], xv, acc0);
        acc1 = fmaf(lin_w[1 * FAN + i], xv, acc1);
        acc2 = fmaf(lin_w[2 * FAN + i], xv, acc2);
        acc3 = fmaf(lin_w[3 * FAN + i], xv, acc3);
    }
#pragma unroll
    for (int off = 16; off > 0; off >>= 1) {
        acc0 += __shfl_xor_sync(0xffffffffu, acc0, off);
        acc1 += __shfl_xor_sync(0xffffffffu, acc1, off);
        acc2 += __shfl_xor_sync(0xffffffffu, acc2, off);
        acc3 += __shfl_xor_sync(0xffffffffu, acc3, off);
    }
    __shared__ float red[8][4];
    int warp = tid >> 5, lane = tid & 31;
    if (lane == 0) {
        red[warp][0] = acc0; red[warp][1] = acc1;
        red[warp][2] = acc2; red[warp][3] = acc3;
    }
    __syncthreads();
    if (tid < 4) {
        float s = 0.f;
#pragma unroll
        for (int wp = 0; wp < 8; wp++) s += red[wp][tid];
        float inp = 0.f;
#pragma unroll
        for (int k = 0; k < 8; k++)
            inp = fmaf(lin_w[tid * FAN + R + k], inputs[n * 8 + k], inp);
        out[n * 4 + tid] = s + inp + lin_b[tid];
    }
}

// ---------------------------------------------------------------------------
// Launch: init -> precompute B -> persistent recurrence -> readout
// ---------------------------------------------------------------------------
extern "C" void kernel_launch(void* const* d_in, const int* in_sizes, int n_in,
                              void* d_out, int out_size) {
    const float* inputs  = (const float*)d_in[0];
    const float* outputs = (const float*)d_in[1];
    const float* w       = (const float*)d_in[2];
    const float* w_in    = (const float*)d_in[3];
    const float* w_feedb = (const float*)d_in[4];
    const float* lin_w   = (const float*)d_in[5];
    const float* lin_b   = (const float*)d_in[6];
    const float* noise   = (const float*)d_in[7];
    float* out = (float*)d_out;

    init_kernel<<<8, 256>>>();
    precomp_kernel<<<dim3(8, 32), 256>>>(inputs, outputs, w_in, w_feedb);
    recur_kernel<<<NBLK, NTHREADS>>>(w, noise);
    readout_kernel<<<T, 256>>>(inputs, lin_w, lin_b, out);
}